// round 7
// baseline (speedup 1.0000x reference)
#include <cuda_runtime.h>

#define BATCH 512
#define NN    4096
#define KK    256
#define EPSF  0.1f
#define MUF   (1.0f / 4096.0f)
#define KF    256.0f
#define L2E   1.4426950408889634f
#define LN2   0.6931471805599453f

#define TPB   256
#define NG    4                  // float4 quad-groups per thread (16 elems)

__device__ float g_rowmax[BATCH];
__device__ unsigned int g_arrive = 0;   // monotonic generation-ticket barrier

__device__ __forceinline__ float frcp(float x) {
    float y; asm("rcp.approx.ftz.f32 %0, %1;" : "=f"(y) : "f"(x)); return y;
}
__device__ __forceinline__ float fex2(float x) {
    float y; asm("ex2.approx.ftz.f32 %0, %1;" : "=f"(y) : "f"(x)); return y;
}
__device__ __forceinline__ float flg2(float x) {
    float y; asm("lg2.approx.ftz.f32 %0, %1;" : "=f"(y) : "f"(x)); return y;
}

// Fused: per-row max -> grid barrier -> global max -> scalar-Newton Sinkhorn -> P.
// All 512 blocks are co-resident (occ 4/SM x 148 SM = 592 slots), so the spin
// barrier cannot deadlock. Ticket generations make it graph-replay safe with
// no reset: launch L's tickets are [512L, 512L+511], everyone spins to 512(L+1).
__global__ void __launch_bounds__(TPB, 4)
fused_kernel(const float* __restrict__ scores, float* __restrict__ out) {
    const int b = blockIdx.x;
    const int t = threadIdx.x;
    const int wrp = t >> 5;
    const int lane = t & 31;

    __shared__ float pre[24];        // scratch: [0:8) max, [8:16) sumr, [16:24) sumr2
    __shared__ float red[2][2][8];   // [parity][T/S2][warp]

    // ---- load row into registers; per-row max of C = max(s^2,(s-1)^2) ----
    const float4* s4 = (const float4*)(scores + b * NN);
    float4 s[NG];
    float m = 0.0f;
#pragma unroll
    for (int g = 0; g < NG; g++) {
        s[g] = s4[g * TPB + t];
        float a0 = s[g].x - 1.0f, a1 = s[g].y - 1.0f;
        float a2 = s[g].z - 1.0f, a3 = s[g].w - 1.0f;
        m = fmaxf(m, fmaxf(fmaxf(s[g].x * s[g].x, a0 * a0), fmaxf(s[g].y * s[g].y, a1 * a1)));
        m = fmaxf(m, fmaxf(fmaxf(s[g].z * s[g].z, a2 * a2), fmaxf(s[g].w * s[g].w, a3 * a3)));
    }
#pragma unroll
    for (int o = 16; o > 0; o >>= 1)
        m = fmaxf(m, __shfl_xor_sync(0xFFFFFFFFu, m, o));
    if (lane == 0) pre[wrp] = m;
    __syncthreads();
    if (t == 0) {
        float x = fmaxf(fmaxf(fmaxf(pre[0], pre[1]), fmaxf(pre[2], pre[3])),
                        fmaxf(fmaxf(pre[4], pre[5]), fmaxf(pre[6], pre[7])));
        g_rowmax[b] = x;
        __threadfence();
        unsigned int ticket = atomicAdd(&g_arrive, 1u);
        unsigned int target = (ticket / BATCH + 1u) * BATCH;
        volatile unsigned int* arr = &g_arrive;
        while (*arr < target) { }
    }
    __syncthreads();   // releases the block once thread 0 passes the barrier

    // ---- global cmax from the 512 row maxes (L2-hot) ----
    m = fmaxf(g_rowmax[t], g_rowmax[t + 256]);
#pragma unroll
    for (int o = 16; o > 0; o >>= 1)
        m = fmaxf(m, __shfl_xor_sync(0xFFFFFFFFu, m, o));
    __syncthreads();   // pre[] reuse
    if (lane == 0) pre[wrp] = m;
    __syncthreads();
    {
        float x = pre[t & 7];
        x = fmaxf(x, __shfl_xor_sync(0xFFFFFFFFu, x, 4));
        x = fmaxf(x, __shfl_xor_sync(0xFFFFFFFFu, x, 2));
        x = fmaxf(x, __shfl_xor_sync(0xFFFFFFFFu, x, 1));
        m = x;
    }
    const float inv = frcp(m * EPSF);          // 1/(cmax*eps)
    const float ca = 2.0f * inv * L2E;         // r = ex2(ca*s + cb)
    const float cb = -inv * L2E;

    // ---- r from register-resident scores; first two moments ----
    float r[4 * NG];
    float sumr = 0.0f, sumr2 = 0.0f;
#pragma unroll
    for (int g = 0; g < NG; g++) {
        float r0 = fex2(fmaf(ca, s[g].x, cb));
        float r1 = fex2(fmaf(ca, s[g].y, cb));
        float r2 = fex2(fmaf(ca, s[g].z, cb));
        float r3 = fex2(fmaf(ca, s[g].w, cb));
        r[4 * g + 0] = r0; r[4 * g + 1] = r1; r[4 * g + 2] = r2; r[4 * g + 3] = r3;
        sumr += (r0 + r1) + (r2 + r3);
        sumr2 = fmaf(r0, r0, fmaf(r1, r1, fmaf(r2, r2, fmaf(r3, r3, sumr2))));
    }
#pragma unroll
    for (int o = 16; o > 0; o >>= 1) {
        sumr  += __shfl_xor_sync(0xFFFFFFFFu, sumr, o);
        sumr2 += __shfl_xor_sync(0xFFFFFFFFu, sumr2, o);
    }
    __syncthreads();
    if (lane == 0) { pre[8 + wrp] = sumr; pre[16 + wrp] = sumr2; }
    __syncthreads();
    {
        float a = pre[8 + (t & 7)];
        float c = pre[16 + (t & 7)];
#pragma unroll
        for (int o = 4; o > 0; o >>= 1) {
            a += __shfl_xor_sync(0xFFFFFFFFu, a, o);
            c += __shfl_xor_sync(0xFFFFFFFFu, c, o);
        }
        sumr = a; sumr2 = c;
    }

    // ---- moment-matched lognormal guess for w ----
    const float m1l = flg2(sumr * MUF);
    const float m2l = flg2(sumr2 * MUF);
    float sig2 = fmaxf(0.0f, (m2l - 2.0f * m1l) * LN2);
    float mu_l = m1l * LN2 - 0.5f * sig2;
    float w = fex2((-mu_l - 1.53412f * sqrtf(sig2)) * L2E);

    // ---- log-domain Newton on T(w) = sum 1/(1+w r) = K ----
    int par = 0;
    for (int it = 0; it < 10; it++) {
        float T = 0.0f, S2 = 0.0f;
#pragma unroll
        for (int g = 0; g < NG; g++) {
            float d0 = fmaf(w, r[4 * g + 0], 1.0f);
            float d1 = fmaf(w, r[4 * g + 1], 1.0f);
            float d2 = fmaf(w, r[4 * g + 2], 1.0f);
            float d3 = fmaf(w, r[4 * g + 3], 1.0f);
            float d01 = d0 * d1, d23 = d2 * d3;
            float rp = frcp(d01 * d23);
            float i0 = d1 * d23 * rp;
            float i1 = d0 * d23 * rp;
            float i2 = d3 * d01 * rp;
            float i3 = d2 * d01 * rp;
            T += (i0 + i1) + (i2 + i3);
            S2 = fmaf(i0, i0, fmaf(i1, i1, fmaf(i2, i2, fmaf(i3, i3, S2))));
        }
#pragma unroll
        for (int o = 16; o > 0; o >>= 1) {
            T  += __shfl_xor_sync(0xFFFFFFFFu, T, o);
            S2 += __shfl_xor_sync(0xFFFFFFFFu, S2, o);
        }
        if (lane == 0) { red[par][0][wrp] = T; red[par][1][wrp] = S2; }
        __syncthreads();
        {
            float x = red[par][0][t & 7];
            float y = red[par][1][t & 7];
#pragma unroll
            for (int o = 4; o > 0; o >>= 1) {
                x += __shfl_xor_sync(0xFFFFFFFFu, x, o);
                y += __shfl_xor_sync(0xFFFFFFFFu, y, o);
            }
            T = x; S2 = y;
        }
        float f = T - KF;
        float slope = fmaxf(T - S2, 1e-6f);     // -dT/dlnw
        float step = fminf(4.0f, fmaxf(-4.0f, f * frcp(slope)));
        w = w * fex2(step * L2E);
        par ^= 1;
        if (fabsf(f) <= 2e-3f) break;           // uniform across block
    }

    // ---- epilogue: P0 = mu/(1+w r) grouped-rcp; streaming stores ----
    float* o0 = out + (size_t)b * 2 * NN;
    float* o1 = o0 + NN;
#pragma unroll
    for (int g = 0; g < NG; g++) {
        float d0 = fmaf(w, r[4 * g + 0], 1.0f);
        float d1 = fmaf(w, r[4 * g + 1], 1.0f);
        float d2 = fmaf(w, r[4 * g + 2], 1.0f);
        float d3 = fmaf(w, r[4 * g + 3], 1.0f);
        float d01 = d0 * d1, d23 = d2 * d3;
        float mrp = MUF * frcp(d01 * d23);
        float4 P0, P1;
        P0.x = d1 * d23 * mrp;
        P0.y = d0 * d23 * mrp;
        P0.z = d3 * d01 * mrp;
        P0.w = d2 * d01 * mrp;
        P1.x = MUF - P0.x;
        P1.y = MUF - P0.y;
        P1.z = MUF - P0.z;
        P1.w = MUF - P0.w;
        __stcs((float4*)(o0) + g * TPB + t, P0);
        __stcs((float4*)(o1) + g * TPB + t, P1);
    }
}

extern "C" void kernel_launch(void* const* d_in, const int* in_sizes, int n_in,
                              void* d_out, int out_size) {
    const float* scores = (const float*)d_in[0];
    float* out = (float*)d_out;
    fused_kernel<<<BATCH, TPB>>>(scores, out);
}